// round 12
// baseline (speedup 1.0000x reference)
#include <cuda_runtime.h>

// Problem shape (fixed by the dataset)
static constexpr int B_TOT = 65536;  // batches
static constexpr int NATOM = 256;    // atoms per frame
static constexpr int A_SEL = 64;     // align indices
static constexpr int M_SEL = 128;    // nn indices
static constexpr int WARPS = 8;      // batches per block (one warp each)
static constexpr int ROWF  = NATOM * 3;  // 768 floats per traj row

__global__ void __launch_bounds__(256, 5)
kabsch_align_kernel(const float* __restrict__ traj,
                    const float* __restrict__ ref_pos,
                    const int*   __restrict__ align_idx,
                    const int*   __restrict__ nn_idx,
                    float*       __restrict__ out)
{
    __shared__ float s_ref[A_SEL * 3];   // centered reference selection
    __shared__ float s_Mc[WARPS][12];    // M (9) + centroid sum (3) per batch
    __shared__ float s_Rc[WARPS][12];    // R (9) + centroid (3) per batch

    const int tid  = threadIdx.x;
    const int w    = tid >> 5;
    const int lane = tid & 31;

    const int b = blockIdx.x * WARPS + w;
    const float* tb = traj + (size_t)b * ROWF;

    // ---- indices straight from gmem (L1/L2-hot broadcast, no barrier dep) ----
    const int a0 = align_idx[lane];
    const int a1 = align_idx[32 + lane];
    const int n0 = nn_idx[lane];
    const int n1 = nn_idx[32 + lane];
    const int n2 = nn_idx[64 + lane];
    const int n3 = nn_idx[96 + lane];

    // ---- front-load ALL 18 value gathers (align + nn): MLP=18, scalar
    //      sorted-window requests (proven optimal R4/R11) ----
    float ax0 = tb[a0 * 3 + 0], ax1 = tb[a0 * 3 + 1], ax2 = tb[a0 * 3 + 2];
    float bx0 = tb[a1 * 3 + 0], bx1 = tb[a1 * 3 + 1], bx2 = tb[a1 * 3 + 2];
    float nx0 = tb[n0 * 3 + 0], nx1 = tb[n0 * 3 + 1], nx2 = tb[n0 * 3 + 2];
    float ny0 = tb[n1 * 3 + 0], ny1 = tb[n1 * 3 + 1], ny2 = tb[n1 * 3 + 2];
    float nz0 = tb[n2 * 3 + 0], nz1 = tb[n2 * 3 + 1], nz2 = tb[n2 * 3 + 2];
    float nw0 = tb[n3 * 3 + 0], nw1 = tb[n3 * 3 + 1], nw2 = tb[n3 * 3 + 2];

    // ---- warp 7 builds the centered reference selection (one barrier) ----
    if (w == 7) {
        float p0 = ref_pos[a0 * 3 + 0];
        float p1 = ref_pos[a0 * 3 + 1];
        float p2 = ref_pos[a0 * 3 + 2];
        float t0 = ref_pos[a1 * 3 + 0];
        float t1 = ref_pos[a1 * 3 + 1];
        float t2 = ref_pos[a1 * 3 + 2];
        float s0 = p0 + t0, s1 = p1 + t1, s2 = p2 + t2;
        #pragma unroll
        for (int o = 16; o > 0; o >>= 1) {
            s0 += __shfl_xor_sync(0xffffffffu, s0, o);
            s1 += __shfl_xor_sync(0xffffffffu, s1, o);
            s2 += __shfl_xor_sync(0xffffffffu, s2, o);
        }
        s0 *= (1.0f / A_SEL); s1 *= (1.0f / A_SEL); s2 *= (1.0f / A_SEL);
        s_ref[lane * 3 + 0] = p0 - s0;
        s_ref[lane * 3 + 1] = p1 - s1;
        s_ref[lane * 3 + 2] = p2 - s2;
        s_ref[(32 + lane) * 3 + 0] = t0 - s0;
        s_ref[(32 + lane) * 3 + 1] = t1 - s1;
        s_ref[(32 + lane) * 3 + 2] = t2 - s2;
    }
    __syncthreads();

    // ---- phase 1: accumulate M and centroid ----
    float r0 = s_ref[lane * 3 + 0];
    float r1 = s_ref[lane * 3 + 1];
    float r2 = s_ref[lane * 3 + 2];
    float q0 = s_ref[(32 + lane) * 3 + 0];
    float q1 = s_ref[(32 + lane) * 3 + 1];
    float q2 = s_ref[(32 + lane) * 3 + 2];

    float c0 = ax0 + bx0, c1 = ax1 + bx1, c2 = ax2 + bx2;
    float m00 = ax0 * r0 + bx0 * q0;
    float m01 = ax0 * r1 + bx0 * q1;
    float m02 = ax0 * r2 + bx0 * q2;
    float m10 = ax1 * r0 + bx1 * q0;
    float m11 = ax1 * r1 + bx1 * q1;
    float m12 = ax1 * r2 + bx1 * q2;
    float m20 = ax2 * r0 + bx2 * q0;
    float m21 = ax2 * r1 + bx2 * q1;
    float m22 = ax2 * r2 + bx2 * q2;

    #pragma unroll
    for (int o = 16; o > 0; o >>= 1) {
        m00 += __shfl_xor_sync(0xffffffffu, m00, o);
        m01 += __shfl_xor_sync(0xffffffffu, m01, o);
        m02 += __shfl_xor_sync(0xffffffffu, m02, o);
        m10 += __shfl_xor_sync(0xffffffffu, m10, o);
        m11 += __shfl_xor_sync(0xffffffffu, m11, o);
        m12 += __shfl_xor_sync(0xffffffffu, m12, o);
        m20 += __shfl_xor_sync(0xffffffffu, m20, o);
        m21 += __shfl_xor_sync(0xffffffffu, m21, o);
        m22 += __shfl_xor_sync(0xffffffffu, m22, o);
        c0  += __shfl_xor_sync(0xffffffffu, c0,  o);
        c1  += __shfl_xor_sync(0xffffffffu, c1,  o);
        c2  += __shfl_xor_sync(0xffffffffu, c2,  o);
    }
    if (lane == 0) {
        s_Mc[w][0] = m00; s_Mc[w][1] = m01; s_Mc[w][2] = m02;
        s_Mc[w][3] = m10; s_Mc[w][4] = m11; s_Mc[w][5] = m12;
        s_Mc[w][6] = m20; s_Mc[w][7] = m21; s_Mc[w][8] = m22;
        s_Mc[w][9] = c0;  s_Mc[w][10] = c1; s_Mc[w][11] = c2;
    }
    __syncthreads();

    // ---- phase 2: 8 solves in parallel (lanes 0..7 of warp 0) ----
    if (tid < WARPS) {
        float M0 = s_Mc[tid][0], M1 = s_Mc[tid][1], M2 = s_Mc[tid][2];
        float M3 = s_Mc[tid][3], M4 = s_Mc[tid][4], M5 = s_Mc[tid][5];
        float M6 = s_Mc[tid][6], M7 = s_Mc[tid][7], M8 = s_Mc[tid][8];

        // Bsym = M^T M (6 unique entries)
        float b00 = M0*M0 + M3*M3 + M6*M6;
        float b01 = M0*M1 + M3*M4 + M6*M7;
        float b02 = M0*M2 + M3*M5 + M6*M8;
        float b11 = M1*M1 + M4*M4 + M7*M7;
        float b12 = M1*M2 + M4*M5 + M7*M8;
        float b22 = M2*M2 + M5*M5 + M8*M8;

        // V = I (v[row][col])
        float v00 = 1.f, v01 = 0.f, v02 = 0.f;
        float v10 = 0.f, v11 = 1.f, v12 = 0.f;
        float v20 = 0.f, v21 = 0.f, v22 = 1.f;

        #pragma unroll
        for (int sweep = 0; sweep < 3; sweep++) {
            // rotate (0,1)
            {
                float apq = b01;
                if (fabsf(apq) > 1e-12f * (fabsf(b00) + fabsf(b11)) + 1e-30f) {
                    float tau = __fdividef((b11 - b00) * 0.5f, apq);
                    float t   = copysignf(1.0f, tau) *
                                __fdividef(1.0f, fabsf(tau) + sqrtf(1.0f + tau * tau));
                    float cc  = rsqrtf(1.0f + t * t);
                    float ss  = t * cc;
                    b00 -= t * apq; b11 += t * apq; b01 = 0.f;
                    float t02 = b02, t12 = b12;
                    b02 = cc * t02 - ss * t12;
                    b12 = ss * t02 + cc * t12;
                    float a, bb;
                    a = v00; bb = v01; v00 = cc * a - ss * bb; v01 = ss * a + cc * bb;
                    a = v10; bb = v11; v10 = cc * a - ss * bb; v11 = ss * a + cc * bb;
                    a = v20; bb = v21; v20 = cc * a - ss * bb; v21 = ss * a + cc * bb;
                }
            }
            // rotate (0,2)
            {
                float apq = b02;
                if (fabsf(apq) > 1e-12f * (fabsf(b00) + fabsf(b22)) + 1e-30f) {
                    float tau = __fdividef((b22 - b00) * 0.5f, apq);
                    float t   = copysignf(1.0f, tau) *
                                __fdividef(1.0f, fabsf(tau) + sqrtf(1.0f + tau * tau));
                    float cc  = rsqrtf(1.0f + t * t);
                    float ss  = t * cc;
                    b00 -= t * apq; b22 += t * apq; b02 = 0.f;
                    float t01 = b01, t12 = b12;
                    b01 = cc * t01 - ss * t12;
                    b12 = ss * t01 + cc * t12;
                    float a, bb;
                    a = v00; bb = v02; v00 = cc * a - ss * bb; v02 = ss * a + cc * bb;
                    a = v10; bb = v12; v10 = cc * a - ss * bb; v12 = ss * a + cc * bb;
                    a = v20; bb = v22; v20 = cc * a - ss * bb; v22 = ss * a + cc * bb;
                }
            }
            // rotate (1,2)
            {
                float apq = b12;
                if (fabsf(apq) > 1e-12f * (fabsf(b11) + fabsf(b22)) + 1e-30f) {
                    float tau = __fdividef((b22 - b11) * 0.5f, apq);
                    float t   = copysignf(1.0f, tau) *
                                __fdividef(1.0f, fabsf(tau) + sqrtf(1.0f + tau * tau));
                    float cc  = rsqrtf(1.0f + t * t);
                    float ss  = t * cc;
                    b11 -= t * apq; b22 += t * apq; b12 = 0.f;
                    float t01 = b01, t02 = b02;
                    b01 = cc * t01 - ss * t02;
                    b02 = ss * t01 + cc * t02;
                    float a, bb;
                    a = v01; bb = v02; v01 = cc * a - ss * bb; v02 = ss * a + cc * bb;
                    a = v11; bb = v12; v11 = cc * a - ss * bb; v12 = ss * a + cc * bb;
                    a = v21; bb = v22; v21 = cc * a - ss * bb; v22 = ss * a + cc * bb;
                }
            }
        }

        // sort eigenpairs descending (columns of V follow)
        float tf;
        if (b00 < b11) { tf=b00; b00=b11; b11=tf;
                         tf=v00; v00=v01; v01=tf;
                         tf=v10; v10=v11; v11=tf;
                         tf=v20; v20=v21; v21=tf; }
        if (b00 < b22) { tf=b00; b00=b22; b22=tf;
                         tf=v00; v00=v02; v02=tf;
                         tf=v10; v10=v12; v12=tf;
                         tf=v20; v20=v22; v22=tf; }
        if (b11 < b22) { tf=b11; b11=b22; b22=tf;
                         tf=v01; v01=v02; v02=tf;
                         tf=v11; v11=v12; v12=tf;
                         tf=v21; v21=v22; v22=tf; }

        // u0 = normalize(M v0), u1 = normalize(M v1 orthogonalized), u2 = u0 x u1
        float u00 = M0*v00 + M1*v10 + M2*v20;
        float u01 = M3*v00 + M4*v10 + M5*v20;
        float u02 = M6*v00 + M7*v10 + M8*v20;
        float inv = rsqrtf(u00*u00 + u01*u01 + u02*u02 + 1e-30f);
        u00 *= inv; u01 *= inv; u02 *= inv;

        float u10 = M0*v01 + M1*v11 + M2*v21;
        float u11 = M3*v01 + M4*v11 + M5*v21;
        float u12 = M6*v01 + M7*v11 + M8*v21;
        float dp = u00*u10 + u01*u11 + u02*u12;
        u10 -= dp * u00; u11 -= dp * u01; u12 -= dp * u02;
        inv = rsqrtf(u10*u10 + u11*u11 + u12*u12 + 1e-30f);
        u10 *= inv; u11 *= inv; u12 *= inv;

        float u20 = u01*u12 - u02*u11;
        float u21 = u02*u10 - u00*u12;
        float u22 = u00*u11 - u01*u10;

        // third reference column = v0 x v1 (forces det(R)=+1 == Kabsch sign fix)
        float w0 = v10*v21 - v20*v11;
        float w1 = v20*v01 - v00*v21;
        float w2 = v00*v11 - v10*v01;

        // R[i][j] = u0[i]*v0[j] + u1[i]*v1[j] + u2[i]*w[j]
        s_Rc[tid][0] = u00*v00 + u10*v01 + u20*w0;
        s_Rc[tid][1] = u00*v10 + u10*v11 + u20*w1;
        s_Rc[tid][2] = u00*v20 + u10*v21 + u20*w2;
        s_Rc[tid][3] = u01*v00 + u11*v01 + u21*w0;
        s_Rc[tid][4] = u01*v10 + u11*v11 + u21*w1;
        s_Rc[tid][5] = u01*v20 + u11*v21 + u21*w2;
        s_Rc[tid][6] = u02*v00 + u12*v01 + u22*w0;
        s_Rc[tid][7] = u02*v10 + u12*v11 + u22*w1;
        s_Rc[tid][8] = u02*v20 + u12*v21 + u22*w2;
        s_Rc[tid][9]  = s_Mc[tid][9]  * (1.0f / A_SEL);
        s_Rc[tid][10] = s_Mc[tid][10] * (1.0f / A_SEL);
        s_Rc[tid][11] = s_Mc[tid][11] * (1.0f / A_SEL);
    }
    __syncthreads();

    // ---- phase 3: rotate the register-resident nn coords; coalesced stores ----
    float R00 = s_Rc[w][0], R01 = s_Rc[w][1], R02 = s_Rc[w][2];
    float R10 = s_Rc[w][3], R11 = s_Rc[w][4], R12 = s_Rc[w][5];
    float R20 = s_Rc[w][6], R21 = s_Rc[w][7], R22 = s_Rc[w][8];
    float cx  = s_Rc[w][9], cy  = s_Rc[w][10], cz = s_Rc[w][11];

    float* ob = out + (size_t)b * (M_SEL * 3);
    {
        float x0 = nx0 - cx, x1 = nx1 - cy, x2 = nx2 - cz;
        int m = lane;
        ob[m * 3 + 0] = x0 * R00 + x1 * R10 + x2 * R20;
        ob[m * 3 + 1] = x0 * R01 + x1 * R11 + x2 * R21;
        ob[m * 3 + 2] = x0 * R02 + x1 * R12 + x2 * R22;
    }
    {
        float x0 = ny0 - cx, x1 = ny1 - cy, x2 = ny2 - cz;
        int m = 32 + lane;
        ob[m * 3 + 0] = x0 * R00 + x1 * R10 + x2 * R20;
        ob[m * 3 + 1] = x0 * R01 + x1 * R11 + x2 * R21;
        ob[m * 3 + 2] = x0 * R02 + x1 * R12 + x2 * R22;
    }
    {
        float x0 = nz0 - cx, x1 = nz1 - cy, x2 = nz2 - cz;
        int m = 64 + lane;
        ob[m * 3 + 0] = x0 * R00 + x1 * R10 + x2 * R20;
        ob[m * 3 + 1] = x0 * R01 + x1 * R11 + x2 * R21;
        ob[m * 3 + 2] = x0 * R02 + x1 * R12 + x2 * R22;
    }
    {
        float x0 = nw0 - cx, x1 = nw1 - cy, x2 = nw2 - cz;
        int m = 96 + lane;
        ob[m * 3 + 0] = x0 * R00 + x1 * R10 + x2 * R20;
        ob[m * 3 + 1] = x0 * R01 + x1 * R11 + x2 * R21;
        ob[m * 3 + 2] = x0 * R02 + x1 * R12 + x2 * R22;
    }
}

extern "C" void kernel_launch(void* const* d_in, const int* in_sizes, int n_in,
                              void* d_out, int out_size)
{
    const float* traj      = (const float*)d_in[0];
    const float* ref_pos   = (const float*)d_in[1];
    const int*   align_idx = (const int*)d_in[2];
    const int*   nn_idx    = (const int*)d_in[3];
    float*       out       = (float*)d_out;

    dim3 grid(B_TOT / WARPS);
    dim3 block(256);
    kabsch_align_kernel<<<grid, block>>>(traj, ref_pos, align_idx, nn_idx, out);
}

// round 13
// speedup vs baseline: 1.0188x; 1.0188x over previous
#include <cuda_runtime.h>

// Problem shape (fixed by the dataset)
static constexpr int B_TOT = 65536;  // batches
static constexpr int NATOM = 256;    // atoms per frame
static constexpr int A_SEL = 64;     // align indices
static constexpr int M_SEL = 128;    // nn indices
static constexpr int WARPS = 8;      // batches per block (one warp each)
static constexpr int ROWF  = NATOM * 3;  // 768 floats per traj row
static constexpr int AFL   = A_SEL * 3;  // 192 selection floats, 6 chunks of 32

__global__ void __launch_bounds__(256, 6)
kabsch_align_kernel(const float* __restrict__ traj,
                    const float* __restrict__ ref_pos,
                    const int*   __restrict__ align_idx,
                    const int*   __restrict__ nn_idx,
                    float*       __restrict__ out)
{
    __shared__ float s_ref[AFL];         // centered reference selection
    __shared__ float s_Mc[WARPS][12];    // M (9) + centroid sum (3) per batch
    __shared__ float s_Rc[WARPS][12];    // R (9) + centroid (3) per batch

    const int tid  = threadIdx.x;
    const int w    = tid >> 5;
    const int lane = tid & 31;

    const int b = blockIdx.x * WARPS + w;
    const float* tb = traj + (size_t)b * ROWF;

    // ---- phase 1 gather, float-split: lane l of chunk k loads sorted float
    //      position p = 32k + l  (address align[p/3]*3 + p%3, strictly
    //      increasing) => each request covers a contiguous ~1/6 of the
    //      selection floats: minimal line touches (no x/y/z re-touch). ----
    int   nk[6], jk[6];
    float vk[6];
    #pragma unroll
    for (int k = 0; k < 6; k++) {
        int p = k * 32 + lane;
        nk[k] = p / 3;               // selection position
        jk[k] = p - 3 * nk[k];       // component 0..2
    }
    int ak[6];
    #pragma unroll
    for (int k = 0; k < 6; k++) ak[k] = align_idx[nk[k]];
    #pragma unroll
    for (int k = 0; k < 6; k++) vk[k] = tb[ak[k] * 3 + jk[k]];

    // ---- warp 7 builds the centered reference selection (one barrier) ----
    if (w == 7) {
        const int a0 = align_idx[lane];
        const int a1 = align_idx[32 + lane];
        float p0 = ref_pos[a0 * 3 + 0];
        float p1 = ref_pos[a0 * 3 + 1];
        float p2 = ref_pos[a0 * 3 + 2];
        float t0 = ref_pos[a1 * 3 + 0];
        float t1 = ref_pos[a1 * 3 + 1];
        float t2 = ref_pos[a1 * 3 + 2];
        float s0 = p0 + t0, s1 = p1 + t1, s2 = p2 + t2;
        #pragma unroll
        for (int o = 16; o > 0; o >>= 1) {
            s0 += __shfl_xor_sync(0xffffffffu, s0, o);
            s1 += __shfl_xor_sync(0xffffffffu, s1, o);
            s2 += __shfl_xor_sync(0xffffffffu, s2, o);
        }
        s0 *= (1.0f / A_SEL); s1 *= (1.0f / A_SEL); s2 *= (1.0f / A_SEL);
        s_ref[lane * 3 + 0] = p0 - s0;
        s_ref[lane * 3 + 1] = p1 - s1;
        s_ref[lane * 3 + 2] = p2 - s2;
        s_ref[(32 + lane) * 3 + 0] = t0 - s0;
        s_ref[(32 + lane) * 3 + 1] = t1 - s1;
        s_ref[(32 + lane) * 3 + 2] = t2 - s2;
    }
    __syncthreads();

    // ---- phase 1 accumulate: mask component into (f0,f1,f2), FMA into
    //      M rows + centroid. Exact same sum as atom-major gather. ----
    float c0 = 0.f, c1 = 0.f, c2 = 0.f;
    float m00 = 0.f, m01 = 0.f, m02 = 0.f;
    float m10 = 0.f, m11 = 0.f, m12 = 0.f;
    float m20 = 0.f, m21 = 0.f, m22 = 0.f;
    #pragma unroll
    for (int k = 0; k < 6; k++) {
        float val = vk[k];
        int   n   = nk[k];
        int   j   = jk[k];
        float w0 = s_ref[n * 3 + 0];
        float w1 = s_ref[n * 3 + 1];
        float w2 = s_ref[n * 3 + 2];
        float f0 = (j == 0) ? val : 0.f;
        float f1 = (j == 1) ? val : 0.f;
        float f2 = (j == 2) ? val : 0.f;
        c0 += f0; c1 += f1; c2 += f2;
        m00 = fmaf(f0, w0, m00); m01 = fmaf(f0, w1, m01); m02 = fmaf(f0, w2, m02);
        m10 = fmaf(f1, w0, m10); m11 = fmaf(f1, w1, m11); m12 = fmaf(f1, w2, m12);
        m20 = fmaf(f2, w0, m20); m21 = fmaf(f2, w1, m21); m22 = fmaf(f2, w2, m22);
    }

    #pragma unroll
    for (int o = 16; o > 0; o >>= 1) {
        m00 += __shfl_xor_sync(0xffffffffu, m00, o);
        m01 += __shfl_xor_sync(0xffffffffu, m01, o);
        m02 += __shfl_xor_sync(0xffffffffu, m02, o);
        m10 += __shfl_xor_sync(0xffffffffu, m10, o);
        m11 += __shfl_xor_sync(0xffffffffu, m11, o);
        m12 += __shfl_xor_sync(0xffffffffu, m12, o);
        m20 += __shfl_xor_sync(0xffffffffu, m20, o);
        m21 += __shfl_xor_sync(0xffffffffu, m21, o);
        m22 += __shfl_xor_sync(0xffffffffu, m22, o);
        c0  += __shfl_xor_sync(0xffffffffu, c0,  o);
        c1  += __shfl_xor_sync(0xffffffffu, c1,  o);
        c2  += __shfl_xor_sync(0xffffffffu, c2,  o);
    }
    if (lane == 0) {
        s_Mc[w][0] = m00; s_Mc[w][1] = m01; s_Mc[w][2] = m02;
        s_Mc[w][3] = m10; s_Mc[w][4] = m11; s_Mc[w][5] = m12;
        s_Mc[w][6] = m20; s_Mc[w][7] = m21; s_Mc[w][8] = m22;
        s_Mc[w][9] = c0;  s_Mc[w][10] = c1; s_Mc[w][11] = c2;
    }
    __syncthreads();

    // ---- phase 2: 8 solves in parallel (lanes 0..7 of warp 0) ----
    if (tid < WARPS) {
        float M0 = s_Mc[tid][0], M1 = s_Mc[tid][1], M2 = s_Mc[tid][2];
        float M3 = s_Mc[tid][3], M4 = s_Mc[tid][4], M5 = s_Mc[tid][5];
        float M6 = s_Mc[tid][6], M7 = s_Mc[tid][7], M8 = s_Mc[tid][8];

        // Bsym = M^T M (6 unique entries)
        float b00 = M0*M0 + M3*M3 + M6*M6;
        float b01 = M0*M1 + M3*M4 + M6*M7;
        float b02 = M0*M2 + M3*M5 + M6*M8;
        float b11 = M1*M1 + M4*M4 + M7*M7;
        float b12 = M1*M2 + M4*M5 + M7*M8;
        float b22 = M2*M2 + M5*M5 + M8*M8;

        // V = I (v[row][col])
        float v00 = 1.f, v01 = 0.f, v02 = 0.f;
        float v10 = 0.f, v11 = 1.f, v12 = 0.f;
        float v20 = 0.f, v21 = 0.f, v22 = 1.f;

        #pragma unroll
        for (int sweep = 0; sweep < 3; sweep++) {
            // rotate (0,1)
            {
                float apq = b01;
                if (fabsf(apq) > 1e-12f * (fabsf(b00) + fabsf(b11)) + 1e-30f) {
                    float tau = __fdividef((b11 - b00) * 0.5f, apq);
                    float t   = copysignf(1.0f, tau) *
                                __fdividef(1.0f, fabsf(tau) + sqrtf(1.0f + tau * tau));
                    float cc  = rsqrtf(1.0f + t * t);
                    float ss  = t * cc;
                    b00 -= t * apq; b11 += t * apq; b01 = 0.f;
                    float t02 = b02, t12 = b12;
                    b02 = cc * t02 - ss * t12;
                    b12 = ss * t02 + cc * t12;
                    float a, bb;
                    a = v00; bb = v01; v00 = cc * a - ss * bb; v01 = ss * a + cc * bb;
                    a = v10; bb = v11; v10 = cc * a - ss * bb; v11 = ss * a + cc * bb;
                    a = v20; bb = v21; v20 = cc * a - ss * bb; v21 = ss * a + cc * bb;
                }
            }
            // rotate (0,2)
            {
                float apq = b02;
                if (fabsf(apq) > 1e-12f * (fabsf(b00) + fabsf(b22)) + 1e-30f) {
                    float tau = __fdividef((b22 - b00) * 0.5f, apq);
                    float t   = copysignf(1.0f, tau) *
                                __fdividef(1.0f, fabsf(tau) + sqrtf(1.0f + tau * tau));
                    float cc  = rsqrtf(1.0f + t * t);
                    float ss  = t * cc;
                    b00 -= t * apq; b22 += t * apq; b02 = 0.f;
                    float t01 = b01, t12 = b12;
                    b01 = cc * t01 - ss * t12;
                    b12 = ss * t01 + cc * t12;
                    float a, bb;
                    a = v00; bb = v02; v00 = cc * a - ss * bb; v02 = ss * a + cc * bb;
                    a = v10; bb = v12; v10 = cc * a - ss * bb; v12 = ss * a + cc * bb;
                    a = v20; bb = v22; v20 = cc * a - ss * bb; v22 = ss * a + cc * bb;
                }
            }
            // rotate (1,2)
            {
                float apq = b12;
                if (fabsf(apq) > 1e-12f * (fabsf(b11) + fabsf(b22)) + 1e-30f) {
                    float tau = __fdividef((b22 - b11) * 0.5f, apq);
                    float t   = copysignf(1.0f, tau) *
                                __fdividef(1.0f, fabsf(tau) + sqrtf(1.0f + tau * tau));
                    float cc  = rsqrtf(1.0f + t * t);
                    float ss  = t * cc;
                    b11 -= t * apq; b22 += t * apq; b12 = 0.f;
                    float t01 = b01, t02 = b02;
                    b01 = cc * t01 - ss * t02;
                    b02 = ss * t01 + cc * t02;
                    float a, bb;
                    a = v01; bb = v02; v01 = cc * a - ss * bb; v02 = ss * a + cc * bb;
                    a = v11; bb = v12; v11 = cc * a - ss * bb; v12 = ss * a + cc * bb;
                    a = v21; bb = v22; v21 = cc * a - ss * bb; v22 = ss * a + cc * bb;
                }
            }
        }

        // sort eigenpairs descending (columns of V follow)
        float tf;
        if (b00 < b11) { tf=b00; b00=b11; b11=tf;
                         tf=v00; v00=v01; v01=tf;
                         tf=v10; v10=v11; v11=tf;
                         tf=v20; v20=v21; v21=tf; }
        if (b00 < b22) { tf=b00; b00=b22; b22=tf;
                         tf=v00; v00=v02; v02=tf;
                         tf=v10; v10=v12; v12=tf;
                         tf=v20; v20=v22; v22=tf; }
        if (b11 < b22) { tf=b11; b11=b22; b22=tf;
                         tf=v01; v01=v02; v02=tf;
                         tf=v11; v11=v12; v12=tf;
                         tf=v21; v21=v22; v22=tf; }

        // u0 = normalize(M v0), u1 = normalize(M v1 orthogonalized), u2 = u0 x u1
        float u00 = M0*v00 + M1*v10 + M2*v20;
        float u01 = M3*v00 + M4*v10 + M5*v20;
        float u02 = M6*v00 + M7*v10 + M8*v20;
        float inv = rsqrtf(u00*u00 + u01*u01 + u02*u02 + 1e-30f);
        u00 *= inv; u01 *= inv; u02 *= inv;

        float u10 = M0*v01 + M1*v11 + M2*v21;
        float u11 = M3*v01 + M4*v11 + M5*v21;
        float u12 = M6*v01 + M7*v11 + M8*v21;
        float dp = u00*u10 + u01*u11 + u02*u12;
        u10 -= dp * u00; u11 -= dp * u01; u12 -= dp * u02;
        inv = rsqrtf(u10*u10 + u11*u11 + u12*u12 + 1e-30f);
        u10 *= inv; u11 *= inv; u12 *= inv;

        float u20 = u01*u12 - u02*u11;
        float u21 = u02*u10 - u00*u12;
        float u22 = u00*u11 - u01*u10;

        // third reference column = v0 x v1 (forces det(R)=+1 == Kabsch sign fix)
        float w0 = v10*v21 - v20*v11;
        float w1 = v20*v01 - v00*v21;
        float w2 = v00*v11 - v10*v01;

        // R[i][j] = u0[i]*v0[j] + u1[i]*v1[j] + u2[i]*w[j]
        s_Rc[tid][0] = u00*v00 + u10*v01 + u20*w0;
        s_Rc[tid][1] = u00*v10 + u10*v11 + u20*w1;
        s_Rc[tid][2] = u00*v20 + u10*v21 + u20*w2;
        s_Rc[tid][3] = u01*v00 + u11*v01 + u21*w0;
        s_Rc[tid][4] = u01*v10 + u11*v11 + u21*w1;
        s_Rc[tid][5] = u01*v20 + u11*v21 + u21*w2;
        s_Rc[tid][6] = u02*v00 + u12*v01 + u22*w0;
        s_Rc[tid][7] = u02*v10 + u12*v11 + u22*w1;
        s_Rc[tid][8] = u02*v20 + u12*v21 + u22*w2;
        s_Rc[tid][9]  = s_Mc[tid][9]  * (1.0f / A_SEL);
        s_Rc[tid][10] = s_Mc[tid][10] * (1.0f / A_SEL);
        s_Rc[tid][11] = s_Mc[tid][11] * (1.0f / A_SEL);
    }
    __syncthreads();

    // ---- phase 3: rotate 128 nn atoms; gathers hit L1 lines fetched by
    //      phase 1; indices straight from gmem (L1-hot) ----
    float R00 = s_Rc[w][0], R01 = s_Rc[w][1], R02 = s_Rc[w][2];
    float R10 = s_Rc[w][3], R11 = s_Rc[w][4], R12 = s_Rc[w][5];
    float R20 = s_Rc[w][6], R21 = s_Rc[w][7], R22 = s_Rc[w][8];
    float cx  = s_Rc[w][9], cy  = s_Rc[w][10], cz = s_Rc[w][11];

    float* ob = out + (size_t)b * (M_SEL * 3);
    #pragma unroll
    for (int k = 0; k < 4; k++) {
        int m = k * 32 + lane;
        int a = nn_idx[m];
        float x0 = tb[a * 3 + 0] - cx;
        float x1 = tb[a * 3 + 1] - cy;
        float x2 = tb[a * 3 + 2] - cz;
        ob[m * 3 + 0] = x0 * R00 + x1 * R10 + x2 * R20;
        ob[m * 3 + 1] = x0 * R01 + x1 * R11 + x2 * R21;
        ob[m * 3 + 2] = x0 * R02 + x1 * R12 + x2 * R22;
    }
}

extern "C" void kernel_launch(void* const* d_in, const int* in_sizes, int n_in,
                              void* d_out, int out_size)
{
    const float* traj      = (const float*)d_in[0];
    const float* ref_pos   = (const float*)d_in[1];
    const int*   align_idx = (const int*)d_in[2];
    const int*   nn_idx    = (const int*)d_in[3];
    float*       out       = (float*)d_out;

    dim3 grid(B_TOT / WARPS);
    dim3 block(256);
    kabsch_align_kernel<<<grid, block>>>(traj, ref_pos, align_idx, nn_idx, out);
}

// round 14
// speedup vs baseline: 1.0550x; 1.0355x over previous
#include <cuda_runtime.h>

// Problem shape (fixed by the dataset)
static constexpr int B_TOT = 65536;  // batches
static constexpr int NATOM = 256;    // atoms per frame
static constexpr int A_SEL = 64;     // align indices
static constexpr int M_SEL = 128;    // nn indices
static constexpr int WARPS = 8;      // batches per block (one warp each)
static constexpr int ROWF  = NATOM * 3;  // 768 floats per traj row
static constexpr int AFL   = A_SEL * 3;  // 192 selection floats, 6 chunks of 32

__global__ void __launch_bounds__(256, 6)
kabsch_align_kernel(const float* __restrict__ traj,
                    const float* __restrict__ ref_pos,
                    const int*   __restrict__ align_idx,
                    const int*   __restrict__ nn_idx,
                    float*       __restrict__ out)
{
    __shared__ float s_ref[AFL];         // centered reference selection
    __shared__ float s_Mc[WARPS][12];    // M (9) + centroid sum (3) per batch
    __shared__ float s_Rc[WARPS][12];    // R (9) + centroid (3) per batch

    const int tid  = threadIdx.x;
    const int w    = tid >> 5;
    const int lane = tid & 31;

    const int b = blockIdx.x * WARPS + w;
    const float* tb = traj + (size_t)b * ROWF;

    // Component j for chunk k at this lane: j = (lane + 2k) mod 3.
    // Chunks {0,3} share jA = r, {1,4} share jB = (r+2)%3, {2,5} share jC = (r+1)%3.
    const int r  = lane % 3;
    const int jA = r;
    const int jB = (r + 2) % 3;
    const int jC = (r + 1) % 3;

    // Selection positions n = p/3 for p = 32k + lane
    const int n0 = lane / 3;
    const int n3 = 32 + n0;             // (96+lane)/3
    const int n1 = (32 + lane) / 3;
    const int n4 = (128 + lane) / 3;
    const int n2 = (64 + lane) / 3;
    const int n5 = (160 + lane) / 3;

    // ---- float-split gather: each request covers a contiguous ~1/6 of the
    //      sorted selection floats => minimal line touches ----
    const int a0 = align_idx[n0];
    const int a1 = align_idx[n1];
    const int a2 = align_idx[n2];
    const int a3 = align_idx[n3];
    const int a4 = align_idx[n4];
    const int a5 = align_idx[n5];
    // preload nn indices too (L1-hot broadcast, off the post-solve path)
    const int nnk0 = nn_idx[lane];
    const int nnk1 = nn_idx[32 + lane];
    const int nnk2 = nn_idx[64 + lane];
    const int nnk3 = nn_idx[96 + lane];

    const float v0 = tb[a0 * 3 + jA];
    const float v1 = tb[a1 * 3 + jB];
    const float v2 = tb[a2 * 3 + jC];
    const float v3 = tb[a3 * 3 + jA];
    const float v4 = tb[a4 * 3 + jB];
    const float v5 = tb[a5 * 3 + jC];

    // ---- warp 7 builds the centered reference selection (one barrier) ----
    if (w == 7) {
        const int b0 = align_idx[lane];
        const int b1 = align_idx[32 + lane];
        float p0 = ref_pos[b0 * 3 + 0];
        float p1 = ref_pos[b0 * 3 + 1];
        float p2 = ref_pos[b0 * 3 + 2];
        float t0 = ref_pos[b1 * 3 + 0];
        float t1 = ref_pos[b1 * 3 + 1];
        float t2 = ref_pos[b1 * 3 + 2];
        float s0 = p0 + t0, s1 = p1 + t1, s2 = p2 + t2;
        #pragma unroll
        for (int o = 16; o > 0; o >>= 1) {
            s0 += __shfl_xor_sync(0xffffffffu, s0, o);
            s1 += __shfl_xor_sync(0xffffffffu, s1, o);
            s2 += __shfl_xor_sync(0xffffffffu, s2, o);
        }
        s0 *= (1.0f / A_SEL); s1 *= (1.0f / A_SEL); s2 *= (1.0f / A_SEL);
        s_ref[lane * 3 + 0] = p0 - s0;
        s_ref[lane * 3 + 1] = p1 - s1;
        s_ref[lane * 3 + 2] = p2 - s2;
        s_ref[(32 + lane) * 3 + 0] = t0 - s0;
        s_ref[(32 + lane) * 3 + 1] = t1 - s1;
        s_ref[(32 + lane) * 3 + 2] = t2 - s2;
    }
    __syncthreads();

    // ---- paired accumulation: three unassigned row-vectors (A,B,C), then
    //      one SEL-permutation into M rows keyed on r = lane%3 ----
    float A0, A1, A2, B0, B1, B2, C0, C1, C2, cA, cB, cC;
    {
        float w0 = s_ref[n0 * 3 + 0], w1 = s_ref[n0 * 3 + 1], w2 = s_ref[n0 * 3 + 2];
        A0 = v0 * w0; A1 = v0 * w1; A2 = v0 * w2;
        w0 = s_ref[n3 * 3 + 0]; w1 = s_ref[n3 * 3 + 1]; w2 = s_ref[n3 * 3 + 2];
        A0 = fmaf(v3, w0, A0); A1 = fmaf(v3, w1, A1); A2 = fmaf(v3, w2, A2);
        cA = v0 + v3;
    }
    {
        float w0 = s_ref[n1 * 3 + 0], w1 = s_ref[n1 * 3 + 1], w2 = s_ref[n1 * 3 + 2];
        B0 = v1 * w0; B1 = v1 * w1; B2 = v1 * w2;
        w0 = s_ref[n4 * 3 + 0]; w1 = s_ref[n4 * 3 + 1]; w2 = s_ref[n4 * 3 + 2];
        B0 = fmaf(v4, w0, B0); B1 = fmaf(v4, w1, B1); B2 = fmaf(v4, w2, B2);
        cB = v1 + v4;
    }
    {
        float w0 = s_ref[n2 * 3 + 0], w1 = s_ref[n2 * 3 + 1], w2 = s_ref[n2 * 3 + 2];
        C0 = v2 * w0; C1 = v2 * w1; C2 = v2 * w2;
        w0 = s_ref[n5 * 3 + 0]; w1 = s_ref[n5 * 3 + 1]; w2 = s_ref[n5 * 3 + 2];
        C0 = fmaf(v5, w0, C0); C1 = fmaf(v5, w1, C1); C2 = fmaf(v5, w2, C2);
        cC = v2 + v5;
    }
    const bool isr0 = (r == 0), isr1 = (r == 1);
    // row0 <- A(r0) / B(r1) / C(r2) ; row1 <- C/A/B ; row2 <- B/C/A
    float m00 = isr0 ? A0 : (isr1 ? B0 : C0);
    float m01 = isr0 ? A1 : (isr1 ? B1 : C1);
    float m02 = isr0 ? A2 : (isr1 ? B2 : C2);
    float m10 = isr0 ? C0 : (isr1 ? A0 : B0);
    float m11 = isr0 ? C1 : (isr1 ? A1 : B1);
    float m12 = isr0 ? C2 : (isr1 ? A2 : B2);
    float m20 = isr0 ? B0 : (isr1 ? C0 : A0);
    float m21 = isr0 ? B1 : (isr1 ? C1 : A1);
    float m22 = isr0 ? B2 : (isr1 ? C2 : A2);
    float c0  = isr0 ? cA : (isr1 ? cB : cC);
    float c1  = isr0 ? cC : (isr1 ? cA : cB);
    float c2  = isr0 ? cB : (isr1 ? cC : cA);

    #pragma unroll
    for (int o = 16; o > 0; o >>= 1) {
        m00 += __shfl_xor_sync(0xffffffffu, m00, o);
        m01 += __shfl_xor_sync(0xffffffffu, m01, o);
        m02 += __shfl_xor_sync(0xffffffffu, m02, o);
        m10 += __shfl_xor_sync(0xffffffffu, m10, o);
        m11 += __shfl_xor_sync(0xffffffffu, m11, o);
        m12 += __shfl_xor_sync(0xffffffffu, m12, o);
        m20 += __shfl_xor_sync(0xffffffffu, m20, o);
        m21 += __shfl_xor_sync(0xffffffffu, m21, o);
        m22 += __shfl_xor_sync(0xffffffffu, m22, o);
        c0  += __shfl_xor_sync(0xffffffffu, c0,  o);
        c1  += __shfl_xor_sync(0xffffffffu, c1,  o);
        c2  += __shfl_xor_sync(0xffffffffu, c2,  o);
    }
    if (lane == 0) {
        s_Mc[w][0] = m00; s_Mc[w][1] = m01; s_Mc[w][2] = m02;
        s_Mc[w][3] = m10; s_Mc[w][4] = m11; s_Mc[w][5] = m12;
        s_Mc[w][6] = m20; s_Mc[w][7] = m21; s_Mc[w][8] = m22;
        s_Mc[w][9] = c0;  s_Mc[w][10] = c1; s_Mc[w][11] = c2;
    }
    __syncthreads();

    // ---- phase 2: 8 solves in parallel (lanes 0..7 of warp 0) ----
    if (tid < WARPS) {
        float M0 = s_Mc[tid][0], M1 = s_Mc[tid][1], M2 = s_Mc[tid][2];
        float M3 = s_Mc[tid][3], M4 = s_Mc[tid][4], M5 = s_Mc[tid][5];
        float M6 = s_Mc[tid][6], M7 = s_Mc[tid][7], M8 = s_Mc[tid][8];

        // Bsym = M^T M (6 unique entries)
        float b00 = M0*M0 + M3*M3 + M6*M6;
        float b01 = M0*M1 + M3*M4 + M6*M7;
        float b02 = M0*M2 + M3*M5 + M6*M8;
        float b11 = M1*M1 + M4*M4 + M7*M7;
        float b12 = M1*M2 + M4*M5 + M7*M8;
        float b22 = M2*M2 + M5*M5 + M8*M8;

        // V = I (v[row][col])
        float v00 = 1.f, v01 = 0.f, v02 = 0.f;
        float v10 = 0.f, v11 = 1.f, v12 = 0.f;
        float v20 = 0.f, v21 = 0.f, v22 = 1.f;

        #pragma unroll
        for (int sweep = 0; sweep < 3; sweep++) {
            // rotate (0,1)
            {
                float apq = b01;
                if (fabsf(apq) > 1e-12f * (fabsf(b00) + fabsf(b11)) + 1e-30f) {
                    float tau = __fdividef((b11 - b00) * 0.5f, apq);
                    float t   = copysignf(1.0f, tau) *
                                __fdividef(1.0f, fabsf(tau) + sqrtf(1.0f + tau * tau));
                    float cc  = rsqrtf(1.0f + t * t);
                    float ss  = t * cc;
                    b00 -= t * apq; b11 += t * apq; b01 = 0.f;
                    float t02 = b02, t12 = b12;
                    b02 = cc * t02 - ss * t12;
                    b12 = ss * t02 + cc * t12;
                    float a, bb;
                    a = v00; bb = v01; v00 = cc * a - ss * bb; v01 = ss * a + cc * bb;
                    a = v10; bb = v11; v10 = cc * a - ss * bb; v11 = ss * a + cc * bb;
                    a = v20; bb = v21; v20 = cc * a - ss * bb; v21 = ss * a + cc * bb;
                }
            }
            // rotate (0,2)
            {
                float apq = b02;
                if (fabsf(apq) > 1e-12f * (fabsf(b00) + fabsf(b22)) + 1e-30f) {
                    float tau = __fdividef((b22 - b00) * 0.5f, apq);
                    float t   = copysignf(1.0f, tau) *
                                __fdividef(1.0f, fabsf(tau) + sqrtf(1.0f + tau * tau));
                    float cc  = rsqrtf(1.0f + t * t);
                    float ss  = t * cc;
                    b00 -= t * apq; b22 += t * apq; b02 = 0.f;
                    float t01 = b01, t12 = b12;
                    b01 = cc * t01 - ss * t12;
                    b12 = ss * t01 + cc * t12;
                    float a, bb;
                    a = v00; bb = v02; v00 = cc * a - ss * bb; v02 = ss * a + cc * bb;
                    a = v10; bb = v12; v10 = cc * a - ss * bb; v12 = ss * a + cc * bb;
                    a = v20; bb = v22; v20 = cc * a - ss * bb; v22 = ss * a + cc * bb;
                }
            }
            // rotate (1,2)
            {
                float apq = b12;
                if (fabsf(apq) > 1e-12f * (fabsf(b11) + fabsf(b22)) + 1e-30f) {
                    float tau = __fdividef((b22 - b11) * 0.5f, apq);
                    float t   = copysignf(1.0f, tau) *
                                __fdividef(1.0f, fabsf(tau) + sqrtf(1.0f + tau * tau));
                    float cc  = rsqrtf(1.0f + t * t);
                    float ss  = t * cc;
                    b11 -= t * apq; b22 += t * apq; b12 = 0.f;
                    float t01 = b01, t02 = b02;
                    b01 = cc * t01 - ss * t02;
                    b02 = ss * t01 + cc * t02;
                    float a, bb;
                    a = v01; bb = v02; v01 = cc * a - ss * bb; v02 = ss * a + cc * bb;
                    a = v11; bb = v12; v11 = cc * a - ss * bb; v12 = ss * a + cc * bb;
                    a = v21; bb = v22; v21 = cc * a - ss * bb; v22 = ss * a + cc * bb;
                }
            }
        }

        // sort eigenpairs descending (columns of V follow)
        float tf;
        if (b00 < b11) { tf=b00; b00=b11; b11=tf;
                         tf=v00; v00=v01; v01=tf;
                         tf=v10; v10=v11; v11=tf;
                         tf=v20; v20=v21; v21=tf; }
        if (b00 < b22) { tf=b00; b00=b22; b22=tf;
                         tf=v00; v00=v02; v02=tf;
                         tf=v10; v10=v12; v12=tf;
                         tf=v20; v20=v22; v22=tf; }
        if (b11 < b22) { tf=b11; b11=b22; b22=tf;
                         tf=v01; v01=v02; v02=tf;
                         tf=v11; v11=v12; v12=tf;
                         tf=v21; v21=v22; v22=tf; }

        // u0 = normalize(M v0), u1 = normalize(M v1 orthogonalized), u2 = u0 x u1
        float u00 = M0*v00 + M1*v10 + M2*v20;
        float u01 = M3*v00 + M4*v10 + M5*v20;
        float u02 = M6*v00 + M7*v10 + M8*v20;
        float inv = rsqrtf(u00*u00 + u01*u01 + u02*u02 + 1e-30f);
        u00 *= inv; u01 *= inv; u02 *= inv;

        float u10 = M0*v01 + M1*v11 + M2*v21;
        float u11 = M3*v01 + M4*v11 + M5*v21;
        float u12 = M6*v01 + M7*v11 + M8*v21;
        float dp = u00*u10 + u01*u11 + u02*u12;
        u10 -= dp * u00; u11 -= dp * u01; u12 -= dp * u02;
        inv = rsqrtf(u10*u10 + u11*u11 + u12*u12 + 1e-30f);
        u10 *= inv; u11 *= inv; u12 *= inv;

        float u20 = u01*u12 - u02*u11;
        float u21 = u02*u10 - u00*u12;
        float u22 = u00*u11 - u01*u10;

        // third reference column = v0 x v1 (forces det(R)=+1 == Kabsch sign fix)
        float w0 = v10*v21 - v20*v11;
        float w1 = v20*v01 - v00*v21;
        float w2 = v00*v11 - v10*v01;

        // R[i][j] = u0[i]*v0[j] + u1[i]*v1[j] + u2[i]*w[j]
        s_Rc[tid][0] = u00*v00 + u10*v01 + u20*w0;
        s_Rc[tid][1] = u00*v10 + u10*v11 + u20*w1;
        s_Rc[tid][2] = u00*v20 + u10*v21 + u20*w2;
        s_Rc[tid][3] = u01*v00 + u11*v01 + u21*w0;
        s_Rc[tid][4] = u01*v10 + u11*v11 + u21*w1;
        s_Rc[tid][5] = u01*v20 + u11*v21 + u21*w2;
        s_Rc[tid][6] = u02*v00 + u12*v01 + u22*w0;
        s_Rc[tid][7] = u02*v10 + u12*v11 + u22*w1;
        s_Rc[tid][8] = u02*v20 + u12*v21 + u22*w2;
        s_Rc[tid][9]  = s_Mc[tid][9]  * (1.0f / A_SEL);
        s_Rc[tid][10] = s_Mc[tid][10] * (1.0f / A_SEL);
        s_Rc[tid][11] = s_Mc[tid][11] * (1.0f / A_SEL);
    }
    __syncthreads();

    // ---- phase 3: rotate 128 nn atoms; gathers hit L1 lines fetched by
    //      phase 1; streaming stores (output never re-read) ----
    float R00 = s_Rc[w][0], R01 = s_Rc[w][1], R02 = s_Rc[w][2];
    float R10 = s_Rc[w][3], R11 = s_Rc[w][4], R12 = s_Rc[w][5];
    float R20 = s_Rc[w][6], R21 = s_Rc[w][7], R22 = s_Rc[w][8];
    float cx  = s_Rc[w][9], cy  = s_Rc[w][10], cz = s_Rc[w][11];

    float* ob = out + (size_t)b * (M_SEL * 3);
    const int nnk[4] = { nnk0, nnk1, nnk2, nnk3 };
    #pragma unroll
    for (int k = 0; k < 4; k++) {
        int m = k * 32 + lane;
        int a = nnk[k];
        float x0 = tb[a * 3 + 0] - cx;
        float x1 = tb[a * 3 + 1] - cy;
        float x2 = tb[a * 3 + 2] - cz;
        __stcs(&ob[m * 3 + 0], x0 * R00 + x1 * R10 + x2 * R20);
        __stcs(&ob[m * 3 + 1], x0 * R01 + x1 * R11 + x2 * R21);
        __stcs(&ob[m * 3 + 2], x0 * R02 + x1 * R12 + x2 * R22);
    }
}

extern "C" void kernel_launch(void* const* d_in, const int* in_sizes, int n_in,
                              void* d_out, int out_size)
{
    const float* traj      = (const float*)d_in[0];
    const float* ref_pos   = (const float*)d_in[1];
    const int*   align_idx = (const int*)d_in[2];
    const int*   nn_idx    = (const int*)d_in[3];
    float*       out       = (float*)d_out;

    dim3 grid(B_TOT / WARPS);
    dim3 block(256);
    kabsch_align_kernel<<<grid, block>>>(traj, ref_pos, align_idx, nn_idx, out);
}

// round 15
// speedup vs baseline: 1.0555x; 1.0005x over previous
#include <cuda_runtime.h>

// Problem shape (fixed by the dataset)
static constexpr int B_TOT = 65536;  // batches
static constexpr int NATOM = 256;    // atoms per frame
static constexpr int A_SEL = 64;     // align indices
static constexpr int M_SEL = 128;    // nn indices
static constexpr int WARPS = 8;      // batches per block (one warp each)
static constexpr int ROWF  = NATOM * 3;  // 768 floats per traj row

__global__ void __launch_bounds__(256, 6)
kabsch_align_kernel(const float* __restrict__ traj,
                    const float* __restrict__ ref_pos,
                    const int*   __restrict__ align_idx,
                    const int*   __restrict__ nn_idx,
                    float*       __restrict__ out)
{
    __shared__ float s_ref[A_SEL * 3];   // centered reference selection
    __shared__ float s_Mc[WARPS][12];    // M (9) + centroid sum (3) per batch
    __shared__ float s_Rc[WARPS][12];    // R (9) + centroid (3) per batch

    const int tid  = threadIdx.x;
    const int w    = tid >> 5;
    const int lane = tid & 31;

    const int b = blockIdx.x * WARPS + w;
    const float* tb = traj + (size_t)b * ROWF;

    // ---- indices straight from gmem (L1/L2-hot broadcast, no barrier dep) ----
    const int a0 = align_idx[lane];
    const int a1 = align_idx[32 + lane];
    const int nn0 = nn_idx[lane];
    const int nn1 = nn_idx[32 + lane];
    const int nn2 = nn_idx[64 + lane];
    const int nn3 = nn_idx[96 + lane];

    // ---- phase 1 gathers issue immediately; consecutive lanes hit
    //      consecutive sorted indices => small line windows ----
    float ax0 = tb[a0 * 3 + 0], ax1 = tb[a0 * 3 + 1], ax2 = tb[a0 * 3 + 2];
    float bx0 = tb[a1 * 3 + 0], bx1 = tb[a1 * 3 + 1], bx2 = tb[a1 * 3 + 2];

    // ---- warp 7 builds the centered reference selection (one barrier) ----
    if (w == 7) {
        float p0 = ref_pos[a0 * 3 + 0];
        float p1 = ref_pos[a0 * 3 + 1];
        float p2 = ref_pos[a0 * 3 + 2];
        float t0 = ref_pos[a1 * 3 + 0];
        float t1 = ref_pos[a1 * 3 + 1];
        float t2 = ref_pos[a1 * 3 + 2];
        float s0 = p0 + t0, s1 = p1 + t1, s2 = p2 + t2;
        #pragma unroll
        for (int o = 16; o > 0; o >>= 1) {
            s0 += __shfl_xor_sync(0xffffffffu, s0, o);
            s1 += __shfl_xor_sync(0xffffffffu, s1, o);
            s2 += __shfl_xor_sync(0xffffffffu, s2, o);
        }
        s0 *= (1.0f / A_SEL); s1 *= (1.0f / A_SEL); s2 *= (1.0f / A_SEL);
        s_ref[lane * 3 + 0] = p0 - s0;
        s_ref[lane * 3 + 1] = p1 - s1;
        s_ref[lane * 3 + 2] = p2 - s2;
        s_ref[(32 + lane) * 3 + 0] = t0 - s0;
        s_ref[(32 + lane) * 3 + 1] = t1 - s1;
        s_ref[(32 + lane) * 3 + 2] = t2 - s2;
    }
    __syncthreads();

    // ---- phase 1: accumulate M and centroid ----
    float r0 = s_ref[lane * 3 + 0];
    float r1 = s_ref[lane * 3 + 1];
    float r2 = s_ref[lane * 3 + 2];
    float q0 = s_ref[(32 + lane) * 3 + 0];
    float q1 = s_ref[(32 + lane) * 3 + 1];
    float q2 = s_ref[(32 + lane) * 3 + 2];

    float c0 = ax0 + bx0, c1 = ax1 + bx1, c2 = ax2 + bx2;
    float m00 = ax0 * r0 + bx0 * q0;
    float m01 = ax0 * r1 + bx0 * q1;
    float m02 = ax0 * r2 + bx0 * q2;
    float m10 = ax1 * r0 + bx1 * q0;
    float m11 = ax1 * r1 + bx1 * q1;
    float m12 = ax1 * r2 + bx1 * q2;
    float m20 = ax2 * r0 + bx2 * q0;
    float m21 = ax2 * r1 + bx2 * q1;
    float m22 = ax2 * r2 + bx2 * q2;

    #pragma unroll
    for (int o = 16; o > 0; o >>= 1) {
        m00 += __shfl_xor_sync(0xffffffffu, m00, o);
        m01 += __shfl_xor_sync(0xffffffffu, m01, o);
        m02 += __shfl_xor_sync(0xffffffffu, m02, o);
        m10 += __shfl_xor_sync(0xffffffffu, m10, o);
        m11 += __shfl_xor_sync(0xffffffffu, m11, o);
        m12 += __shfl_xor_sync(0xffffffffu, m12, o);
        m20 += __shfl_xor_sync(0xffffffffu, m20, o);
        m21 += __shfl_xor_sync(0xffffffffu, m21, o);
        m22 += __shfl_xor_sync(0xffffffffu, m22, o);
        c0  += __shfl_xor_sync(0xffffffffu, c0,  o);
        c1  += __shfl_xor_sync(0xffffffffu, c1,  o);
        c2  += __shfl_xor_sync(0xffffffffu, c2,  o);
    }
    if (lane == 0) {
        s_Mc[w][0] = m00; s_Mc[w][1] = m01; s_Mc[w][2] = m02;
        s_Mc[w][3] = m10; s_Mc[w][4] = m11; s_Mc[w][5] = m12;
        s_Mc[w][6] = m20; s_Mc[w][7] = m21; s_Mc[w][8] = m22;
        s_Mc[w][9] = c0;  s_Mc[w][10] = c1; s_Mc[w][11] = c2;
    }
    __syncthreads();

    // ---- phase 2: 8 solves in parallel (lanes 0..7 of warp 0) ----
    if (tid < WARPS) {
        float M0 = s_Mc[tid][0], M1 = s_Mc[tid][1], M2 = s_Mc[tid][2];
        float M3 = s_Mc[tid][3], M4 = s_Mc[tid][4], M5 = s_Mc[tid][5];
        float M6 = s_Mc[tid][6], M7 = s_Mc[tid][7], M8 = s_Mc[tid][8];

        // Bsym = M^T M (6 unique entries)
        float b00 = M0*M0 + M3*M3 + M6*M6;
        float b01 = M0*M1 + M3*M4 + M6*M7;
        float b02 = M0*M2 + M3*M5 + M6*M8;
        float b11 = M1*M1 + M4*M4 + M7*M7;
        float b12 = M1*M2 + M4*M5 + M7*M8;
        float b22 = M2*M2 + M5*M5 + M8*M8;

        // V = I (v[row][col])
        float v00 = 1.f, v01 = 0.f, v02 = 0.f;
        float v10 = 0.f, v11 = 1.f, v12 = 0.f;
        float v20 = 0.f, v21 = 0.f, v22 = 1.f;

        #pragma unroll
        for (int sweep = 0; sweep < 3; sweep++) {
            // rotate (0,1)
            {
                float apq = b01;
                if (fabsf(apq) > 1e-12f * (fabsf(b00) + fabsf(b11)) + 1e-30f) {
                    float tau = __fdividef((b11 - b00) * 0.5f, apq);
                    float t   = copysignf(1.0f, tau) *
                                __fdividef(1.0f, fabsf(tau) + sqrtf(1.0f + tau * tau));
                    float cc  = rsqrtf(1.0f + t * t);
                    float ss  = t * cc;
                    b00 -= t * apq; b11 += t * apq; b01 = 0.f;
                    float t02 = b02, t12 = b12;
                    b02 = cc * t02 - ss * t12;
                    b12 = ss * t02 + cc * t12;
                    float a, bb;
                    a = v00; bb = v01; v00 = cc * a - ss * bb; v01 = ss * a + cc * bb;
                    a = v10; bb = v11; v10 = cc * a - ss * bb; v11 = ss * a + cc * bb;
                    a = v20; bb = v21; v20 = cc * a - ss * bb; v21 = ss * a + cc * bb;
                }
            }
            // rotate (0,2)
            {
                float apq = b02;
                if (fabsf(apq) > 1e-12f * (fabsf(b00) + fabsf(b22)) + 1e-30f) {
                    float tau = __fdividef((b22 - b00) * 0.5f, apq);
                    float t   = copysignf(1.0f, tau) *
                                __fdividef(1.0f, fabsf(tau) + sqrtf(1.0f + tau * tau));
                    float cc  = rsqrtf(1.0f + t * t);
                    float ss  = t * cc;
                    b00 -= t * apq; b22 += t * apq; b02 = 0.f;
                    float t01 = b01, t12 = b12;
                    b01 = cc * t01 - ss * t12;
                    b12 = ss * t01 + cc * t12;
                    float a, bb;
                    a = v00; bb = v02; v00 = cc * a - ss * bb; v02 = ss * a + cc * bb;
                    a = v10; bb = v12; v10 = cc * a - ss * bb; v12 = ss * a + cc * bb;
                    a = v20; bb = v22; v20 = cc * a - ss * bb; v22 = ss * a + cc * bb;
                }
            }
            // rotate (1,2)
            {
                float apq = b12;
                if (fabsf(apq) > 1e-12f * (fabsf(b11) + fabsf(b22)) + 1e-30f) {
                    float tau = __fdividef((b22 - b11) * 0.5f, apq);
                    float t   = copysignf(1.0f, tau) *
                                __fdividef(1.0f, fabsf(tau) + sqrtf(1.0f + tau * tau));
                    float cc  = rsqrtf(1.0f + t * t);
                    float ss  = t * cc;
                    b11 -= t * apq; b22 += t * apq; b12 = 0.f;
                    float t01 = b01, t02 = b02;
                    b01 = cc * t01 - ss * t02;
                    b02 = ss * t01 + cc * t02;
                    float a, bb;
                    a = v01; bb = v02; v01 = cc * a - ss * bb; v02 = ss * a + cc * bb;
                    a = v11; bb = v12; v11 = cc * a - ss * bb; v12 = ss * a + cc * bb;
                    a = v21; bb = v22; v21 = cc * a - ss * bb; v22 = ss * a + cc * bb;
                }
            }
        }

        // sort eigenpairs descending (columns of V follow)
        float tf;
        if (b00 < b11) { tf=b00; b00=b11; b11=tf;
                         tf=v00; v00=v01; v01=tf;
                         tf=v10; v10=v11; v11=tf;
                         tf=v20; v20=v21; v21=tf; }
        if (b00 < b22) { tf=b00; b00=b22; b22=tf;
                         tf=v00; v00=v02; v02=tf;
                         tf=v10; v10=v12; v12=tf;
                         tf=v20; v20=v22; v22=tf; }
        if (b11 < b22) { tf=b11; b11=b22; b22=tf;
                         tf=v01; v01=v02; v02=tf;
                         tf=v11; v11=v12; v12=tf;
                         tf=v21; v21=v22; v22=tf; }

        // u0 = normalize(M v0), u1 = normalize(M v1 orthogonalized), u2 = u0 x u1
        float u00 = M0*v00 + M1*v10 + M2*v20;
        float u01 = M3*v00 + M4*v10 + M5*v20;
        float u02 = M6*v00 + M7*v10 + M8*v20;
        float inv = rsqrtf(u00*u00 + u01*u01 + u02*u02 + 1e-30f);
        u00 *= inv; u01 *= inv; u02 *= inv;

        float u10 = M0*v01 + M1*v11 + M2*v21;
        float u11 = M3*v01 + M4*v11 + M5*v21;
        float u12 = M6*v01 + M7*v11 + M8*v21;
        float dp = u00*u10 + u01*u11 + u02*u12;
        u10 -= dp * u00; u11 -= dp * u01; u12 -= dp * u02;
        inv = rsqrtf(u10*u10 + u11*u11 + u12*u12 + 1e-30f);
        u10 *= inv; u11 *= inv; u12 *= inv;

        float u20 = u01*u12 - u02*u11;
        float u21 = u02*u10 - u00*u12;
        float u22 = u00*u11 - u01*u10;

        // third reference column = v0 x v1 (forces det(R)=+1 == Kabsch sign fix)
        float w0 = v10*v21 - v20*v11;
        float w1 = v20*v01 - v00*v21;
        float w2 = v00*v11 - v10*v01;

        // R[i][j] = u0[i]*v0[j] + u1[i]*v1[j] + u2[i]*w[j]
        s_Rc[tid][0] = u00*v00 + u10*v01 + u20*w0;
        s_Rc[tid][1] = u00*v10 + u10*v11 + u20*w1;
        s_Rc[tid][2] = u00*v20 + u10*v21 + u20*w2;
        s_Rc[tid][3] = u01*v00 + u11*v01 + u21*w0;
        s_Rc[tid][4] = u01*v10 + u11*v11 + u21*w1;
        s_Rc[tid][5] = u01*v20 + u11*v21 + u21*w2;
        s_Rc[tid][6] = u02*v00 + u12*v01 + u22*w0;
        s_Rc[tid][7] = u02*v10 + u12*v11 + u22*w1;
        s_Rc[tid][8] = u02*v20 + u12*v21 + u22*w2;
        s_Rc[tid][9]  = s_Mc[tid][9]  * (1.0f / A_SEL);
        s_Rc[tid][10] = s_Mc[tid][10] * (1.0f / A_SEL);
        s_Rc[tid][11] = s_Mc[tid][11] * (1.0f / A_SEL);
    }
    __syncthreads();

    // ---- phase 3: rotate 128 nn atoms; gathers hit L1 lines fetched by
    //      phase 1; indices already in registers; streaming stores ----
    float R00 = s_Rc[w][0], R01 = s_Rc[w][1], R02 = s_Rc[w][2];
    float R10 = s_Rc[w][3], R11 = s_Rc[w][4], R12 = s_Rc[w][5];
    float R20 = s_Rc[w][6], R21 = s_Rc[w][7], R22 = s_Rc[w][8];
    float cx  = s_Rc[w][9], cy  = s_Rc[w][10], cz = s_Rc[w][11];

    float* ob = out + (size_t)b * (M_SEL * 3);
    const int nnk[4] = { nn0, nn1, nn2, nn3 };
    #pragma unroll
    for (int k = 0; k < 4; k++) {
        int m = k * 32 + lane;
        int a = nnk[k];
        float x0 = tb[a * 3 + 0] - cx;
        float x1 = tb[a * 3 + 1] - cy;
        float x2 = tb[a * 3 + 2] - cz;
        __stcs(&ob[m * 3 + 0], x0 * R00 + x1 * R10 + x2 * R20);
        __stcs(&ob[m * 3 + 1], x0 * R01 + x1 * R11 + x2 * R21);
        __stcs(&ob[m * 3 + 2], x0 * R02 + x1 * R12 + x2 * R22);
    }
}

extern "C" void kernel_launch(void* const* d_in, const int* in_sizes, int n_in,
                              void* d_out, int out_size)
{
    const float* traj      = (const float*)d_in[0];
    const float* ref_pos   = (const float*)d_in[1];
    const int*   align_idx = (const int*)d_in[2];
    const int*   nn_idx    = (const int*)d_in[3];
    float*       out       = (float*)d_out;

    dim3 grid(B_TOT / WARPS);
    dim3 block(256);
    kabsch_align_kernel<<<grid, block>>>(traj, ref_pos, align_idx, nn_idx, out);
}

// round 16
// speedup vs baseline: 1.0961x; 1.0384x over previous
#include <cuda_runtime.h>

// Problem shape (fixed by the dataset)
static constexpr int B_TOT = 65536;  // batches
static constexpr int NATOM = 256;    // atoms per frame
static constexpr int A_SEL = 64;     // align indices
static constexpr int M_SEL = 128;    // nn indices
static constexpr int BPB   = 16;     // batches per block (2 per warp, 8 warps)
static constexpr int ROWF  = NATOM * 3;  // 768 floats per traj row

__global__ void __launch_bounds__(256, 6)
kabsch_align_kernel(const float* __restrict__ traj,
                    const float* __restrict__ ref_pos,
                    const int*   __restrict__ align_idx,
                    const int*   __restrict__ nn_idx,
                    float*       __restrict__ out)
{
    __shared__ float s_ref[A_SEL * 3];   // centered reference selection
    __shared__ float s_Mc[BPB][12];      // M (9) + centroid sum (3) per batch
    __shared__ float s_Rc[BPB][12];      // R (9) + centroid (3) per batch

    const int tid  = threadIdx.x;
    const int w    = tid >> 5;
    const int lane = tid & 31;

    const int b0 = blockIdx.x * BPB + w * 2;     // this warp's two batches
    const float* tb0 = traj + (size_t)b0 * ROWF;
    const float* tb1 = tb0 + ROWF;

    // ---- align indices (L1/L2-hot broadcast, no barrier dep) ----
    const int a0 = align_idx[lane];
    const int a1 = align_idx[32 + lane];

    // ---- pipelined phase-1 gathers for BOTH batches (MLP = 12);
    //      consecutive lanes hit consecutive sorted indices ----
    float ax0 = tb0[a0 * 3 + 0], ax1 = tb0[a0 * 3 + 1], ax2 = tb0[a0 * 3 + 2];
    float bx0 = tb0[a1 * 3 + 0], bx1 = tb0[a1 * 3 + 1], bx2 = tb0[a1 * 3 + 2];
    float cx0 = tb1[a0 * 3 + 0], cx1 = tb1[a0 * 3 + 1], cx2 = tb1[a0 * 3 + 2];
    float dx0 = tb1[a1 * 3 + 0], dx1 = tb1[a1 * 3 + 1], dx2 = tb1[a1 * 3 + 2];

    // ---- warp 7 builds the centered reference selection (one barrier) ----
    if (w == 7) {
        float p0 = ref_pos[a0 * 3 + 0];
        float p1 = ref_pos[a0 * 3 + 1];
        float p2 = ref_pos[a0 * 3 + 2];
        float t0 = ref_pos[a1 * 3 + 0];
        float t1 = ref_pos[a1 * 3 + 1];
        float t2 = ref_pos[a1 * 3 + 2];
        float s0 = p0 + t0, s1 = p1 + t1, s2 = p2 + t2;
        #pragma unroll
        for (int o = 16; o > 0; o >>= 1) {
            s0 += __shfl_xor_sync(0xffffffffu, s0, o);
            s1 += __shfl_xor_sync(0xffffffffu, s1, o);
            s2 += __shfl_xor_sync(0xffffffffu, s2, o);
        }
        s0 *= (1.0f / A_SEL); s1 *= (1.0f / A_SEL); s2 *= (1.0f / A_SEL);
        s_ref[lane * 3 + 0] = p0 - s0;
        s_ref[lane * 3 + 1] = p1 - s1;
        s_ref[lane * 3 + 2] = p2 - s2;
        s_ref[(32 + lane) * 3 + 0] = t0 - s0;
        s_ref[(32 + lane) * 3 + 1] = t1 - s1;
        s_ref[(32 + lane) * 3 + 2] = t2 - s2;
    }
    __syncthreads();

    const float r0 = s_ref[lane * 3 + 0];
    const float r1 = s_ref[lane * 3 + 1];
    const float r2 = s_ref[lane * 3 + 2];
    const float q0 = s_ref[(32 + lane) * 3 + 0];
    const float q1 = s_ref[(32 + lane) * 3 + 1];
    const float q2 = s_ref[(32 + lane) * 3 + 2];

    // ---- batch 0: accumulate + reduce (b1 gathers still in flight) ----
    {
        float c0 = ax0 + bx0, c1 = ax1 + bx1, c2 = ax2 + bx2;
        float m00 = ax0 * r0 + bx0 * q0;
        float m01 = ax0 * r1 + bx0 * q1;
        float m02 = ax0 * r2 + bx0 * q2;
        float m10 = ax1 * r0 + bx1 * q0;
        float m11 = ax1 * r1 + bx1 * q1;
        float m12 = ax1 * r2 + bx1 * q2;
        float m20 = ax2 * r0 + bx2 * q0;
        float m21 = ax2 * r1 + bx2 * q1;
        float m22 = ax2 * r2 + bx2 * q2;
        #pragma unroll
        for (int o = 16; o > 0; o >>= 1) {
            m00 += __shfl_xor_sync(0xffffffffu, m00, o);
            m01 += __shfl_xor_sync(0xffffffffu, m01, o);
            m02 += __shfl_xor_sync(0xffffffffu, m02, o);
            m10 += __shfl_xor_sync(0xffffffffu, m10, o);
            m11 += __shfl_xor_sync(0xffffffffu, m11, o);
            m12 += __shfl_xor_sync(0xffffffffu, m12, o);
            m20 += __shfl_xor_sync(0xffffffffu, m20, o);
            m21 += __shfl_xor_sync(0xffffffffu, m21, o);
            m22 += __shfl_xor_sync(0xffffffffu, m22, o);
            c0  += __shfl_xor_sync(0xffffffffu, c0,  o);
            c1  += __shfl_xor_sync(0xffffffffu, c1,  o);
            c2  += __shfl_xor_sync(0xffffffffu, c2,  o);
        }
        if (lane == 0) {
            s_Mc[w * 2][0] = m00; s_Mc[w * 2][1] = m01; s_Mc[w * 2][2] = m02;
            s_Mc[w * 2][3] = m10; s_Mc[w * 2][4] = m11; s_Mc[w * 2][5] = m12;
            s_Mc[w * 2][6] = m20; s_Mc[w * 2][7] = m21; s_Mc[w * 2][8] = m22;
            s_Mc[w * 2][9] = c0; s_Mc[w * 2][10] = c1; s_Mc[w * 2][11] = c2;
        }
    }
    // ---- batch 1: accumulate + reduce ----
    {
        float c0 = cx0 + dx0, c1 = cx1 + dx1, c2 = cx2 + dx2;
        float m00 = cx0 * r0 + dx0 * q0;
        float m01 = cx0 * r1 + dx0 * q1;
        float m02 = cx0 * r2 + dx0 * q2;
        float m10 = cx1 * r0 + dx1 * q0;
        float m11 = cx1 * r1 + dx1 * q1;
        float m12 = cx1 * r2 + dx1 * q2;
        float m20 = cx2 * r0 + dx2 * q0;
        float m21 = cx2 * r1 + dx2 * q1;
        float m22 = cx2 * r2 + dx2 * q2;
        #pragma unroll
        for (int o = 16; o > 0; o >>= 1) {
            m00 += __shfl_xor_sync(0xffffffffu, m00, o);
            m01 += __shfl_xor_sync(0xffffffffu, m01, o);
            m02 += __shfl_xor_sync(0xffffffffu, m02, o);
            m10 += __shfl_xor_sync(0xffffffffu, m10, o);
            m11 += __shfl_xor_sync(0xffffffffu, m11, o);
            m12 += __shfl_xor_sync(0xffffffffu, m12, o);
            m20 += __shfl_xor_sync(0xffffffffu, m20, o);
            m21 += __shfl_xor_sync(0xffffffffu, m21, o);
            m22 += __shfl_xor_sync(0xffffffffu, m22, o);
            c0  += __shfl_xor_sync(0xffffffffu, c0,  o);
            c1  += __shfl_xor_sync(0xffffffffu, c1,  o);
            c2  += __shfl_xor_sync(0xffffffffu, c2,  o);
        }
        if (lane == 0) {
            s_Mc[w * 2 + 1][0] = m00; s_Mc[w * 2 + 1][1] = m01; s_Mc[w * 2 + 1][2] = m02;
            s_Mc[w * 2 + 1][3] = m10; s_Mc[w * 2 + 1][4] = m11; s_Mc[w * 2 + 1][5] = m12;
            s_Mc[w * 2 + 1][6] = m20; s_Mc[w * 2 + 1][7] = m21; s_Mc[w * 2 + 1][8] = m22;
            s_Mc[w * 2 + 1][9] = c0; s_Mc[w * 2 + 1][10] = c1; s_Mc[w * 2 + 1][11] = c2;
        }
    }
    __syncthreads();

    // ---- phase 2: 16 solves in parallel (lanes 0..15 of warp 0) ----
    if (tid < BPB) {
        float M0 = s_Mc[tid][0], M1 = s_Mc[tid][1], M2 = s_Mc[tid][2];
        float M3 = s_Mc[tid][3], M4 = s_Mc[tid][4], M5 = s_Mc[tid][5];
        float M6 = s_Mc[tid][6], M7 = s_Mc[tid][7], M8 = s_Mc[tid][8];

        // Bsym = M^T M (6 unique entries)
        float b00 = M0*M0 + M3*M3 + M6*M6;
        float b01 = M0*M1 + M3*M4 + M6*M7;
        float b02 = M0*M2 + M3*M5 + M6*M8;
        float b11 = M1*M1 + M4*M4 + M7*M7;
        float b12 = M1*M2 + M4*M5 + M7*M8;
        float b22 = M2*M2 + M5*M5 + M8*M8;

        // V = I (v[row][col])
        float v00 = 1.f, v01 = 0.f, v02 = 0.f;
        float v10 = 0.f, v11 = 1.f, v12 = 0.f;
        float v20 = 0.f, v21 = 0.f, v22 = 1.f;

        #pragma unroll
        for (int sweep = 0; sweep < 3; sweep++) {
            // rotate (0,1)
            {
                float apq = b01;
                if (fabsf(apq) > 1e-12f * (fabsf(b00) + fabsf(b11)) + 1e-30f) {
                    float tau = __fdividef((b11 - b00) * 0.5f, apq);
                    float t   = copysignf(1.0f, tau) *
                                __fdividef(1.0f, fabsf(tau) + sqrtf(1.0f + tau * tau));
                    float cc  = rsqrtf(1.0f + t * t);
                    float ss  = t * cc;
                    b00 -= t * apq; b11 += t * apq; b01 = 0.f;
                    float t02 = b02, t12 = b12;
                    b02 = cc * t02 - ss * t12;
                    b12 = ss * t02 + cc * t12;
                    float a, bb;
                    a = v00; bb = v01; v00 = cc * a - ss * bb; v01 = ss * a + cc * bb;
                    a = v10; bb = v11; v10 = cc * a - ss * bb; v11 = ss * a + cc * bb;
                    a = v20; bb = v21; v20 = cc * a - ss * bb; v21 = ss * a + cc * bb;
                }
            }
            // rotate (0,2)
            {
                float apq = b02;
                if (fabsf(apq) > 1e-12f * (fabsf(b00) + fabsf(b22)) + 1e-30f) {
                    float tau = __fdividef((b22 - b00) * 0.5f, apq);
                    float t   = copysignf(1.0f, tau) *
                                __fdividef(1.0f, fabsf(tau) + sqrtf(1.0f + tau * tau));
                    float cc  = rsqrtf(1.0f + t * t);
                    float ss  = t * cc;
                    b00 -= t * apq; b22 += t * apq; b02 = 0.f;
                    float t01 = b01, t12 = b12;
                    b01 = cc * t01 - ss * t12;
                    b12 = ss * t01 + cc * t12;
                    float a, bb;
                    a = v00; bb = v02; v00 = cc * a - ss * bb; v02 = ss * a + cc * bb;
                    a = v10; bb = v12; v10 = cc * a - ss * bb; v12 = ss * a + cc * bb;
                    a = v20; bb = v22; v20 = cc * a - ss * bb; v22 = ss * a + cc * bb;
                }
            }
            // rotate (1,2)
            {
                float apq = b12;
                if (fabsf(apq) > 1e-12f * (fabsf(b11) + fabsf(b22)) + 1e-30f) {
                    float tau = __fdividef((b22 - b11) * 0.5f, apq);
                    float t   = copysignf(1.0f, tau) *
                                __fdividef(1.0f, fabsf(tau) + sqrtf(1.0f + tau * tau));
                    float cc  = rsqrtf(1.0f + t * t);
                    float ss  = t * cc;
                    b11 -= t * apq; b22 += t * apq; b12 = 0.f;
                    float t01 = b01, t02 = b02;
                    b01 = cc * t01 - ss * t02;
                    b02 = ss * t01 + cc * t02;
                    float a, bb;
                    a = v01; bb = v02; v01 = cc * a - ss * bb; v02 = ss * a + cc * bb;
                    a = v11; bb = v12; v11 = cc * a - ss * bb; v12 = ss * a + cc * bb;
                    a = v21; bb = v22; v21 = cc * a - ss * bb; v22 = ss * a + cc * bb;
                }
            }
        }

        // sort eigenpairs descending (columns of V follow)
        float tf;
        if (b00 < b11) { tf=b00; b00=b11; b11=tf;
                         tf=v00; v00=v01; v01=tf;
                         tf=v10; v10=v11; v11=tf;
                         tf=v20; v20=v21; v21=tf; }
        if (b00 < b22) { tf=b00; b00=b22; b22=tf;
                         tf=v00; v00=v02; v02=tf;
                         tf=v10; v10=v12; v12=tf;
                         tf=v20; v20=v22; v22=tf; }
        if (b11 < b22) { tf=b11; b11=b22; b22=tf;
                         tf=v01; v01=v02; v02=tf;
                         tf=v11; v11=v12; v12=tf;
                         tf=v21; v21=v22; v22=tf; }

        // u0 = normalize(M v0), u1 = normalize(M v1 orthogonalized), u2 = u0 x u1
        float u00 = M0*v00 + M1*v10 + M2*v20;
        float u01 = M3*v00 + M4*v10 + M5*v20;
        float u02 = M6*v00 + M7*v10 + M8*v20;
        float inv = rsqrtf(u00*u00 + u01*u01 + u02*u02 + 1e-30f);
        u00 *= inv; u01 *= inv; u02 *= inv;

        float u10 = M0*v01 + M1*v11 + M2*v21;
        float u11 = M3*v01 + M4*v11 + M5*v21;
        float u12 = M6*v01 + M7*v11 + M8*v21;
        float dp = u00*u10 + u01*u11 + u02*u12;
        u10 -= dp * u00; u11 -= dp * u01; u12 -= dp * u02;
        inv = rsqrtf(u10*u10 + u11*u11 + u12*u12 + 1e-30f);
        u10 *= inv; u11 *= inv; u12 *= inv;

        float u20 = u01*u12 - u02*u11;
        float u21 = u02*u10 - u00*u12;
        float u22 = u00*u11 - u01*u10;

        // third reference column = v0 x v1 (forces det(R)=+1 == Kabsch sign fix)
        float w0 = v10*v21 - v20*v11;
        float w1 = v20*v01 - v00*v21;
        float w2 = v00*v11 - v10*v01;

        // R[i][j] = u0[i]*v0[j] + u1[i]*v1[j] + u2[i]*w[j]
        s_Rc[tid][0] = u00*v00 + u10*v01 + u20*w0;
        s_Rc[tid][1] = u00*v10 + u10*v11 + u20*w1;
        s_Rc[tid][2] = u00*v20 + u10*v21 + u20*w2;
        s_Rc[tid][3] = u01*v00 + u11*v01 + u21*w0;
        s_Rc[tid][4] = u01*v10 + u11*v11 + u21*w1;
        s_Rc[tid][5] = u01*v20 + u11*v21 + u21*w2;
        s_Rc[tid][6] = u02*v00 + u12*v01 + u22*w0;
        s_Rc[tid][7] = u02*v10 + u12*v11 + u22*w1;
        s_Rc[tid][8] = u02*v20 + u12*v21 + u22*w2;
        s_Rc[tid][9]  = s_Mc[tid][9]  * (1.0f / A_SEL);
        s_Rc[tid][10] = s_Mc[tid][10] * (1.0f / A_SEL);
        s_Rc[tid][11] = s_Mc[tid][11] * (1.0f / A_SEL);
    }
    __syncthreads();

    // ---- phase 3: rotate 128 nn atoms for EACH of the warp's two batches;
    //      gathers hit L1 lines fetched by phase 1 ----
    #pragma unroll
    for (int g = 0; g < 2; g++) {
        const int bat = w * 2 + g;
        const float* tb = (g == 0) ? tb0 : tb1;
        float R00 = s_Rc[bat][0], R01 = s_Rc[bat][1], R02 = s_Rc[bat][2];
        float R10 = s_Rc[bat][3], R11 = s_Rc[bat][4], R12 = s_Rc[bat][5];
        float R20 = s_Rc[bat][6], R21 = s_Rc[bat][7], R22 = s_Rc[bat][8];
        float cx  = s_Rc[bat][9], cy  = s_Rc[bat][10], cz = s_Rc[bat][11];

        float* ob = out + (size_t)(b0 + g) * (M_SEL * 3);
        #pragma unroll
        for (int k = 0; k < 4; k++) {
            int m = k * 32 + lane;
            int a = nn_idx[m];
            float x0 = tb[a * 3 + 0] - cx;
            float x1 = tb[a * 3 + 1] - cy;
            float x2 = tb[a * 3 + 2] - cz;
            __stcs(&ob[m * 3 + 0], x0 * R00 + x1 * R10 + x2 * R20);
            __stcs(&ob[m * 3 + 1], x0 * R01 + x1 * R11 + x2 * R21);
            __stcs(&ob[m * 3 + 2], x0 * R02 + x1 * R12 + x2 * R22);
        }
    }
}

extern "C" void kernel_launch(void* const* d_in, const int* in_sizes, int n_in,
                              void* d_out, int out_size)
{
    const float* traj      = (const float*)d_in[0];
    const float* ref_pos   = (const float*)d_in[1];
    const int*   align_idx = (const int*)d_in[2];
    const int*   nn_idx    = (const int*)d_in[3];
    float*       out       = (float*)d_out;

    dim3 grid(B_TOT / BPB);
    dim3 block(256);
    kabsch_align_kernel<<<grid, block>>>(traj, ref_pos, align_idx, nn_idx, out);
}